// round 1
// baseline (speedup 1.0000x reference)
#include <cuda_runtime.h>
#include <cuda_bf16.h>

#define NN 50000
#define NE 800000
#define INV_SQRT_DEG 0.25f   // 1/sqrt(16)

// ---------------- scratch (static device allocations are allowed) ----------
__device__ float g_s [NN * 16];    // s = node_scalars @ W_in_s
__device__ float g_v [NN * 48];    // v[n][w][c]
__device__ float g_as[NN * 32];    // scalar accumulator
__device__ float g_av[NN * 144];   // vector accumulator, layout [n][(p*3+c)][u(16)]

// ======================= kernel A: node pre + zero ========================
__global__ void __launch_bounds__(256) pre_kernel(
    const float* __restrict__ node_scalars,
    const float* __restrict__ node_vectors,
    const float* __restrict__ W_in_s,
    const float* __restrict__ W_in_v)
{
    __shared__ float sWs[16 * 16];
    __shared__ float sWv[16 * 16];
    for (int i = threadIdx.x; i < 256; i += blockDim.x) {
        sWs[i] = W_in_s[i];
        sWv[i] = W_in_v[i];
    }
    __syncthreads();

    int n = blockIdx.x * blockDim.x + threadIdx.x;
    if (n >= NN) return;

    // load node scalars (16) and vectors (48)
    float nsv[16];
    {
        const float4* p = (const float4*)(node_scalars + (size_t)n * 16);
#pragma unroll
        for (int k = 0; k < 4; k++) {
            float4 q = p[k];
            nsv[4*k+0]=q.x; nsv[4*k+1]=q.y; nsv[4*k+2]=q.z; nsv[4*k+3]=q.w;
        }
    }
    float vin[48];
    {
        const float4* p = (const float4*)(node_vectors + (size_t)n * 48);
#pragma unroll
        for (int k = 0; k < 12; k++) {
            float4 q = p[k];
            vin[4*k+0]=q.x; vin[4*k+1]=q.y; vin[4*k+2]=q.z; vin[4*k+3]=q.w;
        }
    }

    // s[w] = sum_u ns[u] * W_in_s[u][w]
    float sacc[16];
#pragma unroll
    for (int w = 0; w < 16; w++) sacc[w] = 0.f;
#pragma unroll 4
    for (int u = 0; u < 16; u++) {
        float a = nsv[u];
        const float4* row = (const float4*)(sWs + u * 16);
#pragma unroll
        for (int m = 0; m < 4; m++) {
            float4 q = row[m];
            sacc[4*m+0] += a*q.x; sacc[4*m+1] += a*q.y;
            sacc[4*m+2] += a*q.z; sacc[4*m+3] += a*q.w;
        }
    }
    // v[w][c] = sum_u vin[u][c] * W_in_v[u][w]
    float vacc[48];
#pragma unroll
    for (int k = 0; k < 48; k++) vacc[k] = 0.f;
#pragma unroll 2
    for (int u = 0; u < 16; u++) {
        float a0 = vin[u*3+0], a1 = vin[u*3+1], a2 = vin[u*3+2];
        const float* row = sWv + u * 16;
#pragma unroll
        for (int w = 0; w < 16; w++) {
            float ww = row[w];
            vacc[w*3+0] += a0 * ww;
            vacc[w*3+1] += a1 * ww;
            vacc[w*3+2] += a2 * ww;
        }
    }

    // store
    {
        float4* p = (float4*)(g_s + (size_t)n * 16);
#pragma unroll
        for (int k = 0; k < 4; k++)
            p[k] = make_float4(sacc[4*k], sacc[4*k+1], sacc[4*k+2], sacc[4*k+3]);
    }
    {
        float4* p = (float4*)(g_v + (size_t)n * 48);
#pragma unroll
        for (int k = 0; k < 12; k++)
            p[k] = make_float4(vacc[4*k], vacc[4*k+1], vacc[4*k+2], vacc[4*k+3]);
    }
    // zero accumulators
    float4 z = make_float4(0.f, 0.f, 0.f, 0.f);
    {
        float4* p = (float4*)(g_as + (size_t)n * 32);
#pragma unroll
        for (int k = 0; k < 8; k++) p[k] = z;
    }
    {
        float4* p = (float4*)(g_av + (size_t)n * 144);
#pragma unroll
        for (int k = 0; k < 36; k++) p[k] = z;
    }
}

// ======================= kernel B: fused edge kernel ======================
__global__ void __launch_bounds__(256) edge_kernel(
    const float* __restrict__ edge_sh,
    const float* __restrict__ radial_emb,
    const int*   __restrict__ senders,
    const int*   __restrict__ receivers,
    const float* __restrict__ mlp_w1,
    const float* __restrict__ mlp_b1,
    const float* __restrict__ mlp_w2)
{
    __shared__ float s_w1t[64 * 8];   // transposed: [j][i]
    __shared__ float s_b1 [64];
    __shared__ float s_w2 [64 * 80];  // [j][q]

    for (int i = threadIdx.x; i < 8 * 64; i += blockDim.x) {
        int r = i / 64, c = i % 64;     // mlp_w1[r][c]
        s_w1t[c * 8 + r] = mlp_w1[i];
    }
    for (int i = threadIdx.x; i < 64; i += blockDim.x) s_b1[i] = mlp_b1[i];
    for (int i = threadIdx.x; i < 64 * 80; i += blockDim.x) s_w2[i] = mlp_w2[i];
    __syncthreads();

    int e = blockIdx.x * blockDim.x + threadIdx.x;
    if (e >= NE) return;

    // ---- radial MLP: emb(8) -> silu(64) -> wacc(80) ----
    float emb[8];
    {
        const float4* p = (const float4*)(radial_emb + (size_t)e * 8);
        float4 a = p[0], b = p[1];
        emb[0]=a.x; emb[1]=a.y; emb[2]=a.z; emb[3]=a.w;
        emb[4]=b.x; emb[5]=b.y; emb[6]=b.z; emb[7]=b.w;
    }
    float wacc[80];
#pragma unroll
    for (int k = 0; k < 80; k++) wacc[k] = 0.f;

#pragma unroll 2
    for (int j = 0; j < 64; j++) {
        const float4* w1c = (const float4*)(s_w1t + j * 8);
        float4 a = w1c[0], b = w1c[1];
        float h = s_b1[j]
                + emb[0]*a.x + emb[1]*a.y + emb[2]*a.z + emb[3]*a.w
                + emb[4]*b.x + emb[5]*b.y + emb[6]*b.z + emb[7]*b.w;
        // silu
        h = h / (1.f + __expf(-h));
        const float4* w2r = (const float4*)(s_w2 + j * 80);
#pragma unroll
        for (int k = 0; k < 20; k++) {
            float4 q = w2r[k];
            wacc[4*k+0] += h * q.x;
            wacc[4*k+1] += h * q.y;
            wacc[4*k+2] += h * q.z;
            wacc[4*k+3] += h * q.w;
        }
    }

    // ---- messages + scatter ----
    int snd = senders[e];
    int rcv = receivers[e];
    float4 sh4 = *(const float4*)(edge_sh + (size_t)e * 4);
    float Y0 = sh4.x, Yx = sh4.y, Yy = sh4.z, Yz = sh4.w;

    const float4* ps = (const float4*)(g_s + (size_t)snd * 16);
    const float4* pvv = (const float4*)(g_v + (size_t)snd * 48);
    float* as_base = g_as + (size_t)rcv * 32;
    float* av_base = g_av + (size_t)rcv * 144;

#pragma unroll
    for (int ck = 0; ck < 4; ck++) {
        // load this chunk's xs (4) and xv (12)
        float4 xs4 = ps[ck];
        float xs[4] = {xs4.x, xs4.y, xs4.z, xs4.w};
        float xv[12];
        {
            float4 q0 = pvv[3*ck+0], q1 = pvv[3*ck+1], q2 = pvv[3*ck+2];
            xv[0]=q0.x; xv[1]=q0.y; xv[2]=q0.z; xv[3]=q0.w;
            xv[4]=q1.x; xv[5]=q1.y; xv[6]=q1.z; xv[7]=q1.w;
            xv[8]=q2.x; xv[9]=q2.y; xv[10]=q2.z; xv[11]=q2.w;
        }
        float ms1[4], ms2[4], v1[3][4], v2[3][4], v3[3][4];
#pragma unroll
        for (int i = 0; i < 4; i++) {
            int u = 4*ck + i;
            float ax = xv[3*i+0], ay = xv[3*i+1], az = xv[3*i+2];
            float xsu = xs[i];
            ms1[i] = wacc[u] * xsu * Y0;
            ms2[i] = wacc[16+u] * (ax*Yx + ay*Yy + az*Yz);
            float al = wacc[32+u] * xsu;
            v1[0][i] = al * Yx; v1[1][i] = al * Yy; v1[2][i] = al * Yz;
            float be = wacc[48+u] * Y0;
            v2[0][i] = be * ax; v2[1][i] = be * ay; v2[2][i] = be * az;
            float ga = wacc[64+u];
            v3[0][i] = ga * (ay*Yz - az*Yy);
            v3[1][i] = ga * (az*Yx - ax*Yz);
            v3[2][i] = ga * (ax*Yy - ay*Yx);
        }
        atomicAdd((float4*)(as_base + 4*ck),
                  make_float4(ms1[0], ms1[1], ms1[2], ms1[3]));
        atomicAdd((float4*)(as_base + 16 + 4*ck),
                  make_float4(ms2[0], ms2[1], ms2[2], ms2[3]));
#pragma unroll
        for (int c = 0; c < 3; c++) {
            atomicAdd((float4*)(av_base + (0*3 + c) * 16 + 4*ck),
                      make_float4(v1[c][0], v1[c][1], v1[c][2], v1[c][3]));
            atomicAdd((float4*)(av_base + (1*3 + c) * 16 + 4*ck),
                      make_float4(v2[c][0], v2[c][1], v2[c][2], v2[c][3]));
            atomicAdd((float4*)(av_base + (2*3 + c) * 16 + 4*ck),
                      make_float4(v3[c][0], v3[c][1], v3[c][2], v3[c][3]));
        }
    }
}

// ======================= kernel C: node post ==============================
__global__ void __launch_bounds__(256) post_kernel(
    const float* __restrict__ node_scalars,
    const float* __restrict__ node_vectors,
    const int*   __restrict__ species,
    const float* __restrict__ W_out_s,   // [32][32]
    const float* __restrict__ W_out_v,   // [48][16]
    const float* __restrict__ sc_s,      // [4][16][32]
    const float* __restrict__ sc_v,      // [4][16][16]
    float* __restrict__ out)             // [NN][64]
{
    __shared__ float sWs [32 * 32];
    __shared__ float sWv [48 * 16];
    __shared__ float sScs[4 * 16 * 32];
    __shared__ float sScv[4 * 16 * 16];
    for (int i = threadIdx.x; i < 32*32; i += blockDim.x) sWs[i] = W_out_s[i];
    for (int i = threadIdx.x; i < 48*16; i += blockDim.x) sWv[i] = W_out_v[i];
    for (int i = threadIdx.x; i < 4*16*32; i += blockDim.x) sScs[i] = sc_s[i];
    for (int i = threadIdx.x; i < 4*16*16; i += blockDim.x) sScv[i] = sc_v[i];
    __syncthreads();

    int n = blockIdx.x * blockDim.x + threadIdx.x;
    if (n >= NN) return;

    int sp = species[n];

    // pre_s = inv * a_s @ W_out_s + ns @ sc_s[sp]
    float pre_s[32];
#pragma unroll
    for (int w = 0; w < 32; w++) pre_s[w] = 0.f;

    const float* as = g_as + (size_t)n * 32;
#pragma unroll 4
    for (int k = 0; k < 32; k++) {
        float a = as[k] * INV_SQRT_DEG;
        const float4* row = (const float4*)(sWs + k * 32);
#pragma unroll
        for (int m = 0; m < 8; m++) {
            float4 q = row[m];
            pre_s[4*m+0] += a*q.x; pre_s[4*m+1] += a*q.y;
            pre_s[4*m+2] += a*q.z; pre_s[4*m+3] += a*q.w;
        }
    }

    float nsv[16];
    {
        const float4* p = (const float4*)(node_scalars + (size_t)n * 16);
#pragma unroll
        for (int k = 0; k < 4; k++) {
            float4 q = p[k];
            nsv[4*k+0]=q.x; nsv[4*k+1]=q.y; nsv[4*k+2]=q.z; nsv[4*k+3]=q.w;
        }
    }
#pragma unroll 4
    for (int u = 0; u < 16; u++) {
        float a = nsv[u];
        const float4* row = (const float4*)(sScs + (sp * 16 + u) * 32);
#pragma unroll
        for (int m = 0; m < 8; m++) {
            float4 q = row[m];
            pre_s[4*m+0] += a*q.x; pre_s[4*m+1] += a*q.y;
            pre_s[4*m+2] += a*q.z; pre_s[4*m+3] += a*q.w;
        }
    }

    // pre_v[w][c] = inv * sum_k a_v[k][c] * W_out_v[k][w] + sum_u vin[u][c]*sc_v[sp][u][w]
    float pv[48];
#pragma unroll
    for (int k = 0; k < 48; k++) pv[k] = 0.f;

    const float* av = g_av + (size_t)n * 144;
#pragma unroll
    for (int p = 0; p < 3; p++) {
#pragma unroll 2
        for (int u = 0; u < 16; u++) {
            float m0 = av[(p*3 + 0) * 16 + u] * INV_SQRT_DEG;
            float m1 = av[(p*3 + 1) * 16 + u] * INV_SQRT_DEG;
            float m2 = av[(p*3 + 2) * 16 + u] * INV_SQRT_DEG;
            const float* row = sWv + (p * 16 + u) * 16;
#pragma unroll
            for (int w = 0; w < 16; w++) {
                float ww = row[w];
                pv[w*3+0] += ww * m0;
                pv[w*3+1] += ww * m1;
                pv[w*3+2] += ww * m2;
            }
        }
    }

    float vin[48];
    {
        const float4* p = (const float4*)(node_vectors + (size_t)n * 48);
#pragma unroll
        for (int k = 0; k < 12; k++) {
            float4 q = p[k];
            vin[4*k+0]=q.x; vin[4*k+1]=q.y; vin[4*k+2]=q.z; vin[4*k+3]=q.w;
        }
    }
#pragma unroll 2
    for (int u = 0; u < 16; u++) {
        float a0 = vin[u*3+0], a1 = vin[u*3+1], a2 = vin[u*3+2];
        const float* row = sScv + (sp * 16 + u) * 16;
#pragma unroll
        for (int w = 0; w < 16; w++) {
            float ww = row[w];
            pv[w*3+0] += a0 * ww;
            pv[w*3+1] += a1 * ww;
            pv[w*3+2] += a2 * ww;
        }
    }

    // activations + residual + output
    float orow[64];
#pragma unroll
    for (int w = 0; w < 16; w++) {
        float x = pre_s[w];
        orow[w] = x / (1.f + __expf(-x)) + nsv[w];
    }
#pragma unroll
    for (int w = 0; w < 16; w++) {
        float g = 1.f / (1.f + __expf(-pre_s[16 + w]));
        orow[16 + 3*w + 0] = pv[3*w+0] * g + vin[3*w+0];
        orow[16 + 3*w + 1] = pv[3*w+1] * g + vin[3*w+1];
        orow[16 + 3*w + 2] = pv[3*w+2] * g + vin[3*w+2];
    }
    float4* po = (float4*)(out + (size_t)n * 64);
#pragma unroll
    for (int k = 0; k < 16; k++)
        po[k] = make_float4(orow[4*k], orow[4*k+1], orow[4*k+2], orow[4*k+3]);
}

// ======================= launcher ========================================
extern "C" void kernel_launch(void* const* d_in, const int* in_sizes, int n_in,
                              void* d_out, int out_size)
{
    const float* node_scalars = (const float*)d_in[0];
    const float* node_vectors = (const float*)d_in[1];
    const float* edge_sh      = (const float*)d_in[2];
    const float* radial_emb   = (const float*)d_in[3];
    const int*   senders      = (const int*)  d_in[4];
    const int*   receivers    = (const int*)  d_in[5];
    const int*   species      = (const int*)  d_in[6];
    const float* W_in_s       = (const float*)d_in[7];
    const float* W_in_v       = (const float*)d_in[8];
    const float* mlp_w1       = (const float*)d_in[9];
    const float* mlp_b1       = (const float*)d_in[10];
    const float* mlp_w2       = (const float*)d_in[11];
    const float* W_out_s      = (const float*)d_in[12];
    const float* W_out_v      = (const float*)d_in[13];
    const float* sc_s         = (const float*)d_in[14];
    const float* sc_v         = (const float*)d_in[15];
    float* out = (float*)d_out;

    pre_kernel<<<(NN + 255) / 256, 256>>>(node_scalars, node_vectors, W_in_s, W_in_v);
    edge_kernel<<<(NE + 255) / 256, 256>>>(edge_sh, radial_emb, senders, receivers,
                                           mlp_w1, mlp_b1, mlp_w2);
    post_kernel<<<(NN + 255) / 256, 256>>>(node_scalars, node_vectors, species,
                                           W_out_s, W_out_v, sc_s, sc_v, out);
}

// round 3
// speedup vs baseline: 1.0804x; 1.0804x over previous
#include <cuda_runtime.h>
#include <cuda_bf16.h>
#include <cstdint>

#define NN 50000
#define NE 800000
#define INV_SQRT_DEG 0.25f   // 1/sqrt(16)

// ---------------- scratch ----------
__device__ float g_s [NN * 16];    // s = node_scalars @ W_in_s
__device__ float g_v [NN * 48];    // v[n][w][c]
__device__ float g_as[NN * 32];    // scalar accumulator
__device__ float g_av[NN * 144];   // vector accumulator, layout [n][(p*3+c)][u(16)]

// ---------------- f32x2 packed-math helpers (sm_103a FFMA2) ----------------
typedef unsigned long long ull;

__device__ __forceinline__ ull pack2(float x, float y) {
    ull r; asm("mov.b64 %0, {%1, %2};" : "=l"(r) : "f"(x), "f"(y)); return r;
}
__device__ __forceinline__ void unpack2(ull v, float& x, float& y) {
    asm("mov.b64 {%0, %1}, %2;" : "=f"(x), "=f"(y) : "l"(v));
}
__device__ __forceinline__ ull ffma2(ull a, ull b, ull c) {
    ull d; asm("fma.rn.f32x2 %0, %1, %2, %3;" : "=l"(d) : "l"(a), "l"(b), "l"(c));
    return d;
}
__device__ __forceinline__ ull fmul2(ull a, ull b) {
    ull d; asm("mul.rn.f32x2 %0, %1, %2;" : "=l"(d) : "l"(a), "l"(b));
    return d;
}
// LDS.128 into two packed 64-bit halves (addr must be 16B aligned)
__device__ __forceinline__ void lds_v2u64(unsigned int addr, ull& a, ull& b) {
    asm volatile("ld.shared.v2.u64 {%0, %1}, [%2];"
                 : "=l"(a), "=l"(b) : "r"(addr));
}

// ======================= kernel Z: zero accumulators ======================
__global__ void __launch_bounds__(256) zero_kernel()
{
    int i = blockIdx.x * blockDim.x + threadIdx.x;
    float4 z = make_float4(0.f, 0.f, 0.f, 0.f);
    if (i < NN * 36) ((float4*)g_av)[i] = z;
    if (i < NN * 8)  ((float4*)g_as)[i] = z;
}

// ======================= kernel A: node pre ========================
__global__ void __launch_bounds__(256) pre_kernel(
    const float* __restrict__ node_scalars,
    const float* __restrict__ node_vectors,
    const float* __restrict__ W_in_s,
    const float* __restrict__ W_in_v)
{
    __shared__ float sWs[16 * 16];
    __shared__ float sWv[16 * 16];
    for (int i = threadIdx.x; i < 256; i += blockDim.x) {
        sWs[i] = W_in_s[i];
        sWv[i] = W_in_v[i];
    }
    __syncthreads();

    int n = blockIdx.x * blockDim.x + threadIdx.x;
    if (n >= NN) return;

    float nsv[16];
    {
        const float4* p = (const float4*)(node_scalars + (size_t)n * 16);
#pragma unroll
        for (int k = 0; k < 4; k++) {
            float4 q = p[k];
            nsv[4*k+0]=q.x; nsv[4*k+1]=q.y; nsv[4*k+2]=q.z; nsv[4*k+3]=q.w;
        }
    }
    float vin[48];
    {
        const float4* p = (const float4*)(node_vectors + (size_t)n * 48);
#pragma unroll
        for (int k = 0; k < 12; k++) {
            float4 q = p[k];
            vin[4*k+0]=q.x; vin[4*k+1]=q.y; vin[4*k+2]=q.z; vin[4*k+3]=q.w;
        }
    }

    float sacc[16];
#pragma unroll
    for (int w = 0; w < 16; w++) sacc[w] = 0.f;
#pragma unroll 4
    for (int u = 0; u < 16; u++) {
        float a = nsv[u];
        const float4* row = (const float4*)(sWs + u * 16);
#pragma unroll
        for (int m = 0; m < 4; m++) {
            float4 q = row[m];
            sacc[4*m+0] += a*q.x; sacc[4*m+1] += a*q.y;
            sacc[4*m+2] += a*q.z; sacc[4*m+3] += a*q.w;
        }
    }
    float vacc[48];
#pragma unroll
    for (int k = 0; k < 48; k++) vacc[k] = 0.f;
#pragma unroll 2
    for (int u = 0; u < 16; u++) {
        float a0 = vin[u*3+0], a1 = vin[u*3+1], a2 = vin[u*3+2];
        const float* row = sWv + u * 16;
#pragma unroll
        for (int w = 0; w < 16; w++) {
            float ww = row[w];
            vacc[w*3+0] += a0 * ww;
            vacc[w*3+1] += a1 * ww;
            vacc[w*3+2] += a2 * ww;
        }
    }

    {
        float4* p = (float4*)(g_s + (size_t)n * 16);
#pragma unroll
        for (int k = 0; k < 4; k++)
            p[k] = make_float4(sacc[4*k], sacc[4*k+1], sacc[4*k+2], sacc[4*k+3]);
    }
    {
        float4* p = (float4*)(g_v + (size_t)n * 48);
#pragma unroll
        for (int k = 0; k < 12; k++)
            p[k] = make_float4(vacc[4*k], vacc[4*k+1], vacc[4*k+2], vacc[4*k+3]);
    }
}

// ======================= kernel B: fused edge kernel ======================
__global__ void __launch_bounds__(256) edge_kernel(
    const float* __restrict__ edge_sh,
    const float* __restrict__ radial_emb,
    const int*   __restrict__ senders,
    const int*   __restrict__ receivers,
    const float* __restrict__ mlp_w1,
    const float* __restrict__ mlp_b1,
    const float* __restrict__ mlp_w2)
{
    __shared__ __align__(16) float s_w1t[64 * 8];   // transposed: [j][i]
    __shared__ float s_b1 [64];
    __shared__ __align__(16) float s_w2 [64 * 80];  // [j][q]

    for (int i = threadIdx.x; i < 8 * 64; i += blockDim.x) {
        int r = i / 64, c = i % 64;
        s_w1t[c * 8 + r] = mlp_w1[i];
    }
    for (int i = threadIdx.x; i < 64; i += blockDim.x) s_b1[i] = mlp_b1[i];
    for (int i = threadIdx.x; i < 64 * 80; i += blockDim.x) s_w2[i] = mlp_w2[i];
    __syncthreads();

    int e = blockIdx.x * blockDim.x + threadIdx.x;
    if (e >= NE) return;

    unsigned int w1base = (unsigned int)__cvta_generic_to_shared(s_w1t);
    unsigned int w2base = (unsigned int)__cvta_generic_to_shared(s_w2);

    // ---- radial MLP (packed f32x2): emb(8) -> silu(64) -> wacc(80) ----
    ull emb2[4];
    {
        const float4* p = (const float4*)(radial_emb + (size_t)e * 8);
        float4 a = p[0], b = p[1];
        emb2[0] = pack2(a.x, a.y);
        emb2[1] = pack2(a.z, a.w);
        emb2[2] = pack2(b.x, b.y);
        emb2[3] = pack2(b.z, b.w);
    }

    ull wacc2[40];
#pragma unroll
    for (int k = 0; k < 40; k++) wacc2[k] = 0ull;

#pragma unroll 2
    for (int j = 0; j < 64; j++) {
        // first layer: h = b1[j] + dot(emb, w1[:,j])
        ull w1p0, w1p1, w1p2, w1p3;
        lds_v2u64(w1base + j * 32,      w1p0, w1p1);
        lds_v2u64(w1base + j * 32 + 16, w1p2, w1p3);
        ull hp = ffma2(emb2[0], w1p0,
                 ffma2(emb2[1], w1p1,
                 ffma2(emb2[2], w1p2,
                 fmul2(emb2[3], w1p3))));
        float hlo, hhi; unpack2(hp, hlo, hhi);
        float h = s_b1[j] + hlo + hhi;
        // silu
        float sg = __fdividef(h, 1.f + __expf(-h));
        ull hh = pack2(sg, sg);

        // second layer: wacc += sg * w2[j][:]
        unsigned int w2addr = w2base + j * 320;
#pragma unroll
        for (int k = 0; k < 20; k++) {
            ull p0, p1;
            lds_v2u64(w2addr + k * 16, p0, p1);
            wacc2[2*k+0] = ffma2(hh, p0, wacc2[2*k+0]);
            wacc2[2*k+1] = ffma2(hh, p1, wacc2[2*k+1]);
        }
    }

    // unpack weights
    float wv[80];
#pragma unroll
    for (int k = 0; k < 40; k++) unpack2(wacc2[k], wv[2*k], wv[2*k+1]);

    // ---- messages + scatter ----
    int snd = senders[e];
    int rcv = receivers[e];
    float4 sh4 = *(const float4*)(edge_sh + (size_t)e * 4);
    float Y0 = sh4.x, Yx = sh4.y, Yy = sh4.z, Yz = sh4.w;

    const float4* ps  = (const float4*)(g_s + (size_t)snd * 16);
    const float4* pvv = (const float4*)(g_v + (size_t)snd * 48);
    float* as_base = g_as + (size_t)rcv * 32;
    float* av_base = g_av + (size_t)rcv * 144;

#pragma unroll
    for (int ck = 0; ck < 4; ck++) {
        float4 xs4 = ps[ck];
        float xs[4] = {xs4.x, xs4.y, xs4.z, xs4.w};
        float xv[12];
        {
            float4 q0 = pvv[3*ck+0], q1 = pvv[3*ck+1], q2 = pvv[3*ck+2];
            xv[0]=q0.x; xv[1]=q0.y; xv[2]=q0.z; xv[3]=q0.w;
            xv[4]=q1.x; xv[5]=q1.y; xv[6]=q1.z; xv[7]=q1.w;
            xv[8]=q2.x; xv[9]=q2.y; xv[10]=q2.z; xv[11]=q2.w;
        }
        float ms1[4], ms2[4], v1[3][4], v2[3][4], v3[3][4];
#pragma unroll
        for (int i = 0; i < 4; i++) {
            int u = 4*ck + i;
            float ax = xv[3*i+0], ay = xv[3*i+1], az = xv[3*i+2];
            float xsu = xs[i];
            ms1[i] = wv[u] * xsu * Y0;
            ms2[i] = wv[16+u] * (ax*Yx + ay*Yy + az*Yz);
            float al = wv[32+u] * xsu;
            v1[0][i] = al * Yx; v1[1][i] = al * Yy; v1[2][i] = al * Yz;
            float be = wv[48+u] * Y0;
            v2[0][i] = be * ax; v2[1][i] = be * ay; v2[2][i] = be * az;
            float ga = wv[64+u];
            v3[0][i] = ga * (ay*Yz - az*Yy);
            v3[1][i] = ga * (az*Yx - ax*Yz);
            v3[2][i] = ga * (ax*Yy - ay*Yx);
        }
        atomicAdd((float4*)(as_base + 4*ck),
                  make_float4(ms1[0], ms1[1], ms1[2], ms1[3]));
        atomicAdd((float4*)(as_base + 16 + 4*ck),
                  make_float4(ms2[0], ms2[1], ms2[2], ms2[3]));
#pragma unroll
        for (int c = 0; c < 3; c++) {
            atomicAdd((float4*)(av_base + (0*3 + c) * 16 + 4*ck),
                      make_float4(v1[c][0], v1[c][1], v1[c][2], v1[c][3]));
            atomicAdd((float4*)(av_base + (1*3 + c) * 16 + 4*ck),
                      make_float4(v2[c][0], v2[c][1], v2[c][2], v2[c][3]));
            atomicAdd((float4*)(av_base + (2*3 + c) * 16 + 4*ck),
                      make_float4(v3[c][0], v3[c][1], v3[c][2], v3[c][3]));
        }
    }
}

// ======================= kernel C: node post ==============================
__global__ void __launch_bounds__(256) post_kernel(
    const float* __restrict__ node_scalars,
    const float* __restrict__ node_vectors,
    const int*   __restrict__ species,
    const float* __restrict__ W_out_s,   // [32][32]
    const float* __restrict__ W_out_v,   // [48][16]
    const float* __restrict__ sc_s,      // [4][16][32]
    const float* __restrict__ sc_v,      // [4][16][16]
    float* __restrict__ out)             // [NN][64]
{
    __shared__ float sWs [32 * 32];
    __shared__ float sWv [48 * 16];
    __shared__ float sScs[4 * 16 * 32];
    __shared__ float sScv[4 * 16 * 16];
    for (int i = threadIdx.x; i < 32*32; i += blockDim.x) sWs[i] = W_out_s[i];
    for (int i = threadIdx.x; i < 48*16; i += blockDim.x) sWv[i] = W_out_v[i];
    for (int i = threadIdx.x; i < 4*16*32; i += blockDim.x) sScs[i] = sc_s[i];
    for (int i = threadIdx.x; i < 4*16*16; i += blockDim.x) sScv[i] = sc_v[i];
    __syncthreads();

    int n = blockIdx.x * blockDim.x + threadIdx.x;
    if (n >= NN) return;

    int sp = species[n];

    float pre_s[32];
#pragma unroll
    for (int w = 0; w < 32; w++) pre_s[w] = 0.f;

    const float* as = g_as + (size_t)n * 32;
#pragma unroll 4
    for (int k = 0; k < 32; k++) {
        float a = as[k] * INV_SQRT_DEG;
        const float4* row = (const float4*)(sWs + k * 32);
#pragma unroll
        for (int m = 0; m < 8; m++) {
            float4 q = row[m];
            pre_s[4*m+0] += a*q.x; pre_s[4*m+1] += a*q.y;
            pre_s[4*m+2] += a*q.z; pre_s[4*m+3] += a*q.w;
        }
    }

    float nsv[16];
    {
        const float4* p = (const float4*)(node_scalars + (size_t)n * 16);
#pragma unroll
        for (int k = 0; k < 4; k++) {
            float4 q = p[k];
            nsv[4*k+0]=q.x; nsv[4*k+1]=q.y; nsv[4*k+2]=q.z; nsv[4*k+3]=q.w;
        }
    }
#pragma unroll 4
    for (int u = 0; u < 16; u++) {
        float a = nsv[u];
        const float4* row = (const float4*)(sScs + (sp * 16 + u) * 32);
#pragma unroll
        for (int m = 0; m < 8; m++) {
            float4 q = row[m];
            pre_s[4*m+0] += a*q.x; pre_s[4*m+1] += a*q.y;
            pre_s[4*m+2] += a*q.z; pre_s[4*m+3] += a*q.w;
        }
    }

    float pv[48];
#pragma unroll
    for (int k = 0; k < 48; k++) pv[k] = 0.f;

    const float* av = g_av + (size_t)n * 144;
#pragma unroll
    for (int p = 0; p < 3; p++) {
#pragma unroll 2
        for (int u = 0; u < 16; u++) {
            float m0 = av[(p*3 + 0) * 16 + u] * INV_SQRT_DEG;
            float m1 = av[(p*3 + 1) * 16 + u] * INV_SQRT_DEG;
            float m2 = av[(p*3 + 2) * 16 + u] * INV_SQRT_DEG;
            const float* row = sWv + (p * 16 + u) * 16;
#pragma unroll
            for (int w = 0; w < 16; w++) {
                float ww = row[w];
                pv[w*3+0] += ww * m0;
                pv[w*3+1] += ww * m1;
                pv[w*3+2] += ww * m2;
            }
        }
    }

    float vin[48];
    {
        const float4* p = (const float4*)(node_vectors + (size_t)n * 48);
#pragma unroll
        for (int k = 0; k < 12; k++) {
            float4 q = p[k];
            vin[4*k+0]=q.x; vin[4*k+1]=q.y; vin[4*k+2]=q.z; vin[4*k+3]=q.w;
        }
    }
#pragma unroll 2
    for (int u = 0; u < 16; u++) {
        float a0 = vin[u*3+0], a1 = vin[u*3+1], a2 = vin[u*3+2];
        const float* row = sScv + (sp * 16 + u) * 16;
#pragma unroll
        for (int w = 0; w < 16; w++) {
            float ww = row[w];
            pv[w*3+0] += a0 * ww;
            pv[w*3+1] += a1 * ww;
            pv[w*3+2] += a2 * ww;
        }
    }

    float orow[64];
#pragma unroll
    for (int w = 0; w < 16; w++) {
        float x = pre_s[w];
        orow[w] = x / (1.f + __expf(-x)) + nsv[w];
    }
#pragma unroll
    for (int w = 0; w < 16; w++) {
        float g = 1.f / (1.f + __expf(-pre_s[16 + w]));
        orow[16 + 3*w + 0] = pv[3*w+0] * g + vin[3*w+0];
        orow[16 + 3*w + 1] = pv[3*w+1] * g + vin[3*w+1];
        orow[16 + 3*w + 2] = pv[3*w+2] * g + vin[3*w+2];
    }
    float4* po = (float4*)(out + (size_t)n * 64);
#pragma unroll
    for (int k = 0; k < 16; k++)
        po[k] = make_float4(orow[4*k], orow[4*k+1], orow[4*k+2], orow[4*k+3]);
}

// ======================= launcher ========================================
extern "C" void kernel_launch(void* const* d_in, const int* in_sizes, int n_in,
                              void* d_out, int out_size)
{
    const float* node_scalars = (const float*)d_in[0];
    const float* node_vectors = (const float*)d_in[1];
    const float* edge_sh      = (const float*)d_in[2];
    const float* radial_emb   = (const float*)d_in[3];
    const int*   senders      = (const int*)  d_in[4];
    const int*   receivers    = (const int*)  d_in[5];
    const int*   species      = (const int*)  d_in[6];
    const float* W_in_s       = (const float*)d_in[7];
    const float* W_in_v       = (const float*)d_in[8];
    const float* mlp_w1       = (const float*)d_in[9];
    const float* mlp_b1       = (const float*)d_in[10];
    const float* mlp_w2       = (const float*)d_in[11];
    const float* W_out_s      = (const float*)d_in[12];
    const float* W_out_v      = (const float*)d_in[13];
    const float* sc_s         = (const float*)d_in[14];
    const float* sc_v         = (const float*)d_in[15];
    float* out = (float*)d_out;

    zero_kernel<<<(NN * 36 + 255) / 256, 256>>>();
    pre_kernel<<<(NN + 255) / 256, 256>>>(node_scalars, node_vectors, W_in_s, W_in_v);
    edge_kernel<<<(NE + 255) / 256, 256>>>(edge_sh, radial_emb, senders, receivers,
                                           mlp_w1, mlp_b1, mlp_w2);
    post_kernel<<<(NN + 255) / 256, 256>>>(node_scalars, node_vectors, species,
                                           W_out_s, W_out_v, sc_s, sc_v, out);
}

// round 5
// speedup vs baseline: 1.1786x; 1.0908x over previous
#include <cuda_runtime.h>
#include <cuda_bf16.h>
#include <cstdint>

#define NN 50000
#define NE 800000
#define INV_SQRT_DEG 0.25f   // 1/sqrt(16)

// ---------------- scratch ----------
__device__ float g_s [NN * 16];    // s = node_scalars @ W_in_s
__device__ float g_v [NN * 48];    // v[n][w][c]
__device__ float g_as[NN * 32];    // scalar accumulator
__device__ float g_av[NN * 144];   // vector accumulator [n][(p*3+c)][u(16)]

// ---------------- f32x2 packed-math helpers (sm_103a FFMA2) ----------------
typedef unsigned long long ull;

__device__ __forceinline__ ull pack2(float x, float y) {
    ull r; asm("mov.b64 %0, {%1, %2};" : "=l"(r) : "f"(x), "f"(y)); return r;
}
__device__ __forceinline__ void unpack2(ull v, float& x, float& y) {
    asm("mov.b64 {%0, %1}, %2;" : "=f"(x), "=f"(y) : "l"(v));
}
__device__ __forceinline__ ull ffma2(ull a, ull b, ull c) {
    ull d; asm("fma.rn.f32x2 %0, %1, %2, %3;" : "=l"(d) : "l"(a), "l"(b), "l"(c));
    return d;
}
__device__ __forceinline__ ull fmul2(ull a, ull b) {
    ull d; asm("mul.rn.f32x2 %0, %1, %2;" : "=l"(d) : "l"(a), "l"(b));
    return d;
}
// 16B shared load as two packed f32x2 halves
__device__ __forceinline__ void lds_v2u64(unsigned int addr, ull& a, ull& b) {
    asm volatile("ld.shared.v2.u64 {%0, %1}, [%2];"
                 : "=l"(a), "=l"(b) : "r"(addr));
}

// ======================= kernel Z: zero accumulators ======================
__global__ void __launch_bounds__(256) zero_kernel()
{
    int i = blockIdx.x * blockDim.x + threadIdx.x;
    float4 z = make_float4(0.f, 0.f, 0.f, 0.f);
    if (i < NN * 36) ((float4*)g_av)[i] = z;
    if (i < NN * 8)  ((float4*)g_as)[i] = z;
}

// ======================= kernel A: node pre (2 threads / node) ============
__global__ void __launch_bounds__(256) pre_kernel(
    const float* __restrict__ node_scalars,
    const float* __restrict__ node_vectors,
    const float* __restrict__ W_in_s,
    const float* __restrict__ W_in_v)
{
    __shared__ __align__(16) float sWs[16 * 16];
    __shared__ __align__(16) float sWv[16 * 16];
    for (int i = threadIdx.x; i < 256; i += blockDim.x) {
        sWs[i] = W_in_s[i];
        sWv[i] = W_in_v[i];
    }
    __syncthreads();

    int t = blockIdx.x * blockDim.x + threadIdx.x;
    int n = t >> 1;
    int h = t & 1;           // output half: w in [8h, 8h+8)
    if (n >= NN) return;

    unsigned int wsb = (unsigned int)__cvta_generic_to_shared(sWs) + h * 32;
    unsigned int wvb = (unsigned int)__cvta_generic_to_shared(sWv) + h * 32;

    float nsv[16];
    {
        const float4* p = (const float4*)(node_scalars + (size_t)n * 16);
#pragma unroll
        for (int k = 0; k < 4; k++) {
            float4 q = p[k];
            nsv[4*k+0]=q.x; nsv[4*k+1]=q.y; nsv[4*k+2]=q.z; nsv[4*k+3]=q.w;
        }
    }
    float vin[48];
    {
        const float4* p = (const float4*)(node_vectors + (size_t)n * 48);
#pragma unroll
        for (int k = 0; k < 12; k++) {
            float4 q = p[k];
            vin[4*k+0]=q.x; vin[4*k+1]=q.y; vin[4*k+2]=q.z; vin[4*k+3]=q.w;
        }
    }

    ull sacc2[4];
#pragma unroll
    for (int q = 0; q < 4; q++) sacc2[q] = 0ull;
    ull vacc2[3][4];
#pragma unroll
    for (int c = 0; c < 3; c++)
#pragma unroll
        for (int q = 0; q < 4; q++) vacc2[c][q] = 0ull;

#pragma unroll 4
    for (int u = 0; u < 16; u++) {
        ull w0, w1;
        lds_v2u64(wsb + u * 64,      w0, w1);   // W_in_s[u][8h..8h+4)
        ull w2, w3;
        lds_v2u64(wsb + u * 64 + 16, w2, w3);   // W_in_s[u][8h+4..8h+8)
        ull aa = pack2(nsv[u], nsv[u]);
        sacc2[0] = ffma2(aa, w0, sacc2[0]);
        sacc2[1] = ffma2(aa, w1, sacc2[1]);
        sacc2[2] = ffma2(aa, w2, sacc2[2]);
        sacc2[3] = ffma2(aa, w3, sacc2[3]);

        ull v0, v1, v2, v3;
        lds_v2u64(wvb + u * 64,      v0, v1);
        lds_v2u64(wvb + u * 64 + 16, v2, v3);
#pragma unroll
        for (int c = 0; c < 3; c++) {
            ull mm = pack2(vin[u*3+c], vin[u*3+c]);
            vacc2[c][0] = ffma2(mm, v0, vacc2[c][0]);
            vacc2[c][1] = ffma2(mm, v1, vacc2[c][1]);
            vacc2[c][2] = ffma2(mm, v2, vacc2[c][2]);
            vacc2[c][3] = ffma2(mm, v3, vacc2[c][3]);
        }
    }

    // store s half
    {
        float s8[8];
#pragma unroll
        for (int q = 0; q < 4; q++) unpack2(sacc2[q], s8[2*q], s8[2*q+1]);
        float4* p = (float4*)(g_s + (size_t)n * 16 + 8*h);
        p[0] = make_float4(s8[0], s8[1], s8[2], s8[3]);
        p[1] = make_float4(s8[4], s8[5], s8[6], s8[7]);
    }
    // store v half: g_v[n][w][c], w in [8h,8h+8) -> floats [24h, 24h+24)
    {
        float vv[3][8];
#pragma unroll
        for (int c = 0; c < 3; c++)
#pragma unroll
            for (int q = 0; q < 4; q++) unpack2(vacc2[c][q], vv[c][2*q], vv[c][2*q+1]);
        float out24[24];
#pragma unroll
        for (int w = 0; w < 8; w++) {
            out24[3*w+0] = vv[0][w];
            out24[3*w+1] = vv[1][w];
            out24[3*w+2] = vv[2][w];
        }
        float4* p = (float4*)(g_v + (size_t)n * 48 + 24*h);
#pragma unroll
        for (int k = 0; k < 6; k++)
            p[k] = make_float4(out24[4*k], out24[4*k+1], out24[4*k+2], out24[4*k+3]);
    }
}

// ======================= kernel B: fused edge kernel (2 threads / edge) ===
__global__ void __launch_bounds__(256) edge_kernel(
    const float* __restrict__ edge_sh,
    const float* __restrict__ radial_emb,
    const int*   __restrict__ senders,
    const int*   __restrict__ receivers,
    const float* __restrict__ mlp_w1,
    const float* __restrict__ mlp_b1,
    const float* __restrict__ mlp_w2)
{
    __shared__ __align__(16) float s_w1t[64 * 8];   // transposed: [j][i]
    __shared__ float s_b1 [64];
    __shared__ __align__(16) float s_w2 [64 * 80];  // [j][q]

    for (int i = threadIdx.x; i < 8 * 64; i += blockDim.x) {
        int r = i / 64, c = i % 64;
        s_w1t[c * 8 + r] = mlp_w1[i];
    }
    for (int i = threadIdx.x; i < 64; i += blockDim.x) s_b1[i] = mlp_b1[i];
    for (int i = threadIdx.x; i < 64 * 80; i += blockDim.x) s_w2[i] = mlp_w2[i];
    __syncthreads();

    int t = blockIdx.x * blockDim.x + threadIdx.x;
    int e = t >> 1;
    int h = t & 1;           // u-half: u in [8h, 8h+8)
    if (e >= NE) return;

    unsigned int w1base = (unsigned int)__cvta_generic_to_shared(s_w1t);
    unsigned int w2off  = (unsigned int)__cvta_generic_to_shared(s_w2) + h * 32;

    // ---- radial MLP (f32x2): emb(8) -> silu(64) -> this thread's 40 outputs
    ull emb2[4];
    {
        const float4* p = (const float4*)(radial_emb + (size_t)e * 8);
        float4 a = p[0], b = p[1];
        emb2[0] = pack2(a.x, a.y);
        emb2[1] = pack2(a.z, a.w);
        emb2[2] = pack2(b.x, b.y);
        emb2[3] = pack2(b.z, b.w);
    }

    ull wacc2[20];
#pragma unroll
    for (int k = 0; k < 20; k++) wacc2[k] = 0ull;

#pragma unroll 2
    for (int j = 0; j < 64; j++) {
        ull w1p0, w1p1, w1p2, w1p3;
        lds_v2u64(w1base + j * 32,      w1p0, w1p1);
        lds_v2u64(w1base + j * 32 + 16, w1p2, w1p3);
        ull hp = ffma2(emb2[0], w1p0,
                 ffma2(emb2[1], w1p1,
                 ffma2(emb2[2], w1p2,
                 fmul2(emb2[3], w1p3))));
        float hlo, hhi; unpack2(hp, hlo, hhi);
        float hv = s_b1[j] + hlo + hhi;
        float sg = __fdividef(hv, 1.f + __expf(-hv));
        ull hh = pack2(sg, sg);

        unsigned int a = w2off + j * 320;
#pragma unroll
        for (int p = 0; p < 5; p++) {
            ull p0, p1, p2, p3;
            lds_v2u64(a + p * 64,      p0, p1);
            lds_v2u64(a + p * 64 + 16, p2, p3);
            wacc2[4*p+0] = ffma2(hh, p0, wacc2[4*p+0]);
            wacc2[4*p+1] = ffma2(hh, p1, wacc2[4*p+1]);
            wacc2[4*p+2] = ffma2(hh, p2, wacc2[4*p+2]);
            wacc2[4*p+3] = ffma2(hh, p3, wacc2[4*p+3]);
        }
    }

    // unpack: wvl[p][lu], lu in [0,8) corresponds to u = 8h + lu
    float wvl[5][8];
#pragma unroll
    for (int p = 0; p < 5; p++)
#pragma unroll
        for (int q = 0; q < 4; q++)
            unpack2(wacc2[4*p+q], wvl[p][2*q], wvl[p][2*q+1]);

    // ---- messages + scatter (this thread's u-half: chunks ck = 2h, 2h+1) --
    int snd = senders[e];
    int rcv = receivers[e];
    float4 sh4 = *(const float4*)(edge_sh + (size_t)e * 4);
    float Y0 = sh4.x, Yx = sh4.y, Yy = sh4.z, Yz = sh4.w;

    const float4* ps  = (const float4*)(g_s + (size_t)snd * 16);
    const float4* pvv = (const float4*)(g_v + (size_t)snd * 48);
    float* as_base = g_as + (size_t)rcv * 32;
    float* av_base = g_av + (size_t)rcv * 144;

#pragma unroll
    for (int cc = 0; cc < 2; cc++) {
        int ck = 2*h + cc;
        float4 xs4 = ps[ck];
        float xs[4] = {xs4.x, xs4.y, xs4.z, xs4.w};
        float xv[12];
        {
            float4 q0 = pvv[3*ck+0], q1 = pvv[3*ck+1], q2 = pvv[3*ck+2];
            xv[0]=q0.x; xv[1]=q0.y; xv[2]=q0.z; xv[3]=q0.w;
            xv[4]=q1.x; xv[5]=q1.y; xv[6]=q1.z; xv[7]=q1.w;
            xv[8]=q2.x; xv[9]=q2.y; xv[10]=q2.z; xv[11]=q2.w;
        }
        float ms1[4], ms2[4], v1[3][4], v2[3][4], v3[3][4];
#pragma unroll
        for (int i = 0; i < 4; i++) {
            int lu = 4*cc + i;
            float ax = xv[3*i+0], ay = xv[3*i+1], az = xv[3*i+2];
            float xsu = xs[i];
            ms1[i] = wvl[0][lu] * xsu * Y0;
            ms2[i] = wvl[1][lu] * (ax*Yx + ay*Yy + az*Yz);
            float al = wvl[2][lu] * xsu;
            v1[0][i] = al * Yx; v1[1][i] = al * Yy; v1[2][i] = al * Yz;
            float be = wvl[3][lu] * Y0;
            v2[0][i] = be * ax; v2[1][i] = be * ay; v2[2][i] = be * az;
            float ga = wvl[4][lu];
            v3[0][i] = ga * (ay*Yz - az*Yy);
            v3[1][i] = ga * (az*Yx - ax*Yz);
            v3[2][i] = ga * (ax*Yy - ay*Yx);
        }
        atomicAdd((float4*)(as_base + 4*ck),
                  make_float4(ms1[0], ms1[1], ms1[2], ms1[3]));
        atomicAdd((float4*)(as_base + 16 + 4*ck),
                  make_float4(ms2[0], ms2[1], ms2[2], ms2[3]));
#pragma unroll
        for (int c = 0; c < 3; c++) {
            atomicAdd((float4*)(av_base + (0*3 + c) * 16 + 4*ck),
                      make_float4(v1[c][0], v1[c][1], v1[c][2], v1[c][3]));
            atomicAdd((float4*)(av_base + (1*3 + c) * 16 + 4*ck),
                      make_float4(v2[c][0], v2[c][1], v2[c][2], v2[c][3]));
            atomicAdd((float4*)(av_base + (2*3 + c) * 16 + 4*ck),
                      make_float4(v3[c][0], v3[c][1], v3[c][2], v3[c][3]));
        }
    }
}

// ======================= kernel C: node post (2 threads / node) ===========
__global__ void __launch_bounds__(256) post_kernel(
    const float* __restrict__ node_scalars,
    const float* __restrict__ node_vectors,
    const int*   __restrict__ species,
    const float* __restrict__ W_out_s,   // [32][32]
    const float* __restrict__ W_out_v,   // [48][16]
    const float* __restrict__ sc_s,      // [4][16][32]
    const float* __restrict__ sc_v,      // [4][16][16]
    float* __restrict__ out)             // [NN][64]
{
    __shared__ __align__(16) float sWs [32 * 32];
    __shared__ __align__(16) float sWv [48 * 16];
    __shared__ __align__(16) float sScs[4 * 16 * 32];
    __shared__ __align__(16) float sScv[4 * 16 * 16];
    for (int i = threadIdx.x; i < 32*32; i += blockDim.x) sWs[i] = W_out_s[i];
    for (int i = threadIdx.x; i < 48*16; i += blockDim.x) sWv[i] = W_out_v[i];
    for (int i = threadIdx.x; i < 4*16*32; i += blockDim.x) sScs[i] = sc_s[i];
    for (int i = threadIdx.x; i < 4*16*16; i += blockDim.x) sScv[i] = sc_v[i];
    __syncthreads();

    int t = blockIdx.x * blockDim.x + threadIdx.x;
    int n = t >> 1;
    int h = t & 1;           // w-half: w in [8h, 8h+8)
    if (n >= NN) return;

    int sp = species[n];

    unsigned int wsb  = (unsigned int)__cvta_generic_to_shared(sWs)  + h * 32;
    unsigned int wvb  = (unsigned int)__cvta_generic_to_shared(sWv)  + h * 32;
    unsigned int scsb = (unsigned int)__cvta_generic_to_shared(sScs) + sp * 2048 + h * 32;
    unsigned int scvb = (unsigned int)__cvta_generic_to_shared(sScv) + sp * 1024 + h * 32;

    // accumulators: 8 silu outs (cols 8h..8h+8), 8 gate outs (cols 16+8h..)
    ull psa[4], psg[4];
#pragma unroll
    for (int q = 0; q < 4; q++) { psa[q] = 0ull; psg[q] = 0ull; }

    // a_s @ W_out_s (half columns)
    {
        float asv[32];
        const float4* p = (const float4*)(g_as + (size_t)n * 32);
#pragma unroll
        for (int k = 0; k < 8; k++) {
            float4 q = p[k];
            asv[4*k+0]=q.x; asv[4*k+1]=q.y; asv[4*k+2]=q.z; asv[4*k+3]=q.w;
        }
#pragma unroll 4
        for (int k = 0; k < 32; k++) {
            float a = asv[k] * INV_SQRT_DEG;
            ull aa = pack2(a, a);
            ull r0, r1, r2, r3;
            lds_v2u64(wsb + k * 128,      r0, r1);   // cols [8h,8h+8)
            lds_v2u64(wsb + k * 128 + 64, r2, r3);   // cols [16+8h,16+8h+8)
            psa[0] = ffma2(aa, r0, psa[0]);
            psa[1] = ffma2(aa, r1, psa[1]);
            psg[0] = ffma2(aa, r2, psg[0]);
            psg[1] = ffma2(aa, r3, psg[1]);
            lds_v2u64(wsb + k * 128 + 16, r0, r1);
            lds_v2u64(wsb + k * 128 + 80, r2, r3);
            psa[2] = ffma2(aa, r0, psa[2]);
            psa[3] = ffma2(aa, r1, psa[3]);
            psg[2] = ffma2(aa, r2, psg[2]);
            psg[3] = ffma2(aa, r3, psg[3]);
        }
    }

    // + node_scalars @ sc_s[sp]
    float nsv[16];
    {
        const float4* p = (const float4*)(node_scalars + (size_t)n * 16);
#pragma unroll
        for (int k = 0; k < 4; k++) {
            float4 q = p[k];
            nsv[4*k+0]=q.x; nsv[4*k+1]=q.y; nsv[4*k+2]=q.z; nsv[4*k+3]=q.w;
        }
    }
#pragma unroll 4
    for (int u = 0; u < 16; u++) {
        ull aa = pack2(nsv[u], nsv[u]);
        ull r0, r1, r2, r3;
        lds_v2u64(scsb + u * 128,      r0, r1);
        lds_v2u64(scsb + u * 128 + 64, r2, r3);
        psa[0] = ffma2(aa, r0, psa[0]);
        psa[1] = ffma2(aa, r1, psa[1]);
        psg[0] = ffma2(aa, r2, psg[0]);
        psg[1] = ffma2(aa, r3, psg[1]);
        lds_v2u64(scsb + u * 128 + 16, r0, r1);
        lds_v2u64(scsb + u * 128 + 80, r2, r3);
        psa[2] = ffma2(aa, r0, psa[2]);
        psa[3] = ffma2(aa, r1, psa[3]);
        psg[2] = ffma2(aa, r2, psg[2]);
        psg[3] = ffma2(aa, r3, psg[3]);
    }

    // pv[c][w-half]: a_v @ W_out_v + vin @ sc_v[sp]
    ull pv2[3][4];
#pragma unroll
    for (int c = 0; c < 3; c++)
#pragma unroll
        for (int q = 0; q < 4; q++) pv2[c][q] = 0ull;

    const float* av = g_av + (size_t)n * 144;
#pragma unroll
    for (int p = 0; p < 3; p++) {
        float m0[16], m1[16], m2[16];
        {
            const float4* q0 = (const float4*)(av + (p*3+0)*16);
            const float4* q1 = (const float4*)(av + (p*3+1)*16);
            const float4* q2 = (const float4*)(av + (p*3+2)*16);
#pragma unroll
            for (int k = 0; k < 4; k++) {
                float4 a = q0[k]; m0[4*k]=a.x; m0[4*k+1]=a.y; m0[4*k+2]=a.z; m0[4*k+3]=a.w;
                float4 b = q1[k]; m1[4*k]=b.x; m1[4*k+1]=b.y; m1[4*k+2]=b.z; m1[4*k+3]=b.w;
                float4 c4 = q2[k]; m2[4*k]=c4.x; m2[4*k+1]=c4.y; m2[4*k+2]=c4.z; m2[4*k+3]=c4.w;
            }
        }
#pragma unroll 4
        for (int u = 0; u < 16; u++) {
            ull r0, r1, r2, r3;
            lds_v2u64(wvb + (p*16 + u) * 64,      r0, r1);
            lds_v2u64(wvb + (p*16 + u) * 64 + 16, r2, r3);
            ull mm0 = pack2(m0[u]*INV_SQRT_DEG, m0[u]*INV_SQRT_DEG);
            ull mm1 = pack2(m1[u]*INV_SQRT_DEG, m1[u]*INV_SQRT_DEG);
            ull mm2 = pack2(m2[u]*INV_SQRT_DEG, m2[u]*INV_SQRT_DEG);
            pv2[0][0] = ffma2(mm0, r0, pv2[0][0]);
            pv2[0][1] = ffma2(mm0, r1, pv2[0][1]);
            pv2[0][2] = ffma2(mm0, r2, pv2[0][2]);
            pv2[0][3] = ffma2(mm0, r3, pv2[0][3]);
            pv2[1][0] = ffma2(mm1, r0, pv2[1][0]);
            pv2[1][1] = ffma2(mm1, r1, pv2[1][1]);
            pv2[1][2] = ffma2(mm1, r2, pv2[1][2]);
            pv2[1][3] = ffma2(mm1, r3, pv2[1][3]);
            pv2[2][0] = ffma2(mm2, r0, pv2[2][0]);
            pv2[2][1] = ffma2(mm2, r1, pv2[2][1]);
            pv2[2][2] = ffma2(mm2, r2, pv2[2][2]);
            pv2[2][3] = ffma2(mm2, r3, pv2[2][3]);
        }
    }

    float vin[48];
    {
        const float4* p = (const float4*)(node_vectors + (size_t)n * 48);
#pragma unroll
        for (int k = 0; k < 12; k++) {
            float4 q = p[k];
            vin[4*k+0]=q.x; vin[4*k+1]=q.y; vin[4*k+2]=q.z; vin[4*k+3]=q.w;
        }
    }
#pragma unroll 4
    for (int u = 0; u < 16; u++) {
        ull r0, r1, r2, r3;
        lds_v2u64(scvb + u * 64,      r0, r1);
        lds_v2u64(scvb + u * 64 + 16, r2, r3);
        ull mm0 = pack2(vin[u*3+0], vin[u*3+0]);
        ull mm1 = pack2(vin[u*3+1], vin[u*3+1]);
        ull mm2 = pack2(vin[u*3+2], vin[u*3+2]);
        pv2[0][0] = ffma2(mm0, r0, pv2[0][0]);
        pv2[0][1] = ffma2(mm0, r1, pv2[0][1]);
        pv2[0][2] = ffma2(mm0, r2, pv2[0][2]);
        pv2[0][3] = ffma2(mm0, r3, pv2[0][3]);
        pv2[1][0] = ffma2(mm1, r0, pv2[1][0]);
        pv2[1][1] = ffma2(mm1, r1, pv2[1][1]);
        pv2[1][2] = ffma2(mm1, r2, pv2[1][2]);
        pv2[1][3] = ffma2(mm1, r3, pv2[1][3]);
        pv2[2][0] = ffma2(mm2, r0, pv2[2][0]);
        pv2[2][1] = ffma2(mm2, r1, pv2[2][1]);
        pv2[2][2] = ffma2(mm2, r2, pv2[2][2]);
        pv2[2][3] = ffma2(mm2, r3, pv2[2][3]);
    }

    // activations + residual + output
    float sa[8], sg[8], pvv[3][8];
#pragma unroll
    for (int q = 0; q < 4; q++) {
        unpack2(psa[q], sa[2*q], sa[2*q+1]);
        unpack2(psg[q], sg[2*q], sg[2*q+1]);
    }
#pragma unroll
    for (int c = 0; c < 3; c++)
#pragma unroll
        for (int q = 0; q < 4; q++)
            unpack2(pv2[c][q], pvv[c][2*q], pvv[c][2*q+1]);

    // out_s half: out[n][8h..8h+8)
    {
        float o8[8];
#pragma unroll
        for (int i = 0; i < 8; i++) {
            float x = sa[i];
            o8[i] = __fdividef(x, 1.f + __expf(-x)) + nsv[8*h + i];
        }
        float4* p = (float4*)(out + (size_t)n * 64 + 8*h);
        p[0] = make_float4(o8[0], o8[1], o8[2], o8[3]);
        p[1] = make_float4(o8[4], o8[5], o8[6], o8[7]);
    }
    // out_v half: out[n][16 + 3w + c] for w in [8h,8h+8) -> floats [16+24h, +24)
    {
        float o24[24];
#pragma unroll
        for (int i = 0; i < 8; i++) {
            float g = __fdividef(1.f, 1.f + __expf(-sg[i]));
            int w = 8*h + i;
            o24[3*i+0] = pvv[0][i] * g + vin[3*w+0];
            o24[3*i+1] = pvv[1][i] * g + vin[3*w+1];
            o24[3*i+2] = pvv[2][i] * g + vin[3*w+2];
        }
        float4* p = (float4*)(out + (size_t)n * 64 + 16 + 24*h);
#pragma unroll
        for (int k = 0; k < 6; k++)
            p[k] = make_float4(o24[4*k], o24[4*k+1], o24[4*k+2], o24[4*k+3]);
    }
}

// ======================= launcher ========================================
extern "C" void kernel_launch(void* const* d_in, const int* in_sizes, int n_in,
                              void* d_out, int out_size)
{
    const float* node_scalars = (const float*)d_in[0];
    const float* node_vectors = (const float*)d_in[1];
    const float* edge_sh      = (const float*)d_in[2];
    const float* radial_emb   = (const float*)d_in[3];
    const int*   senders      = (const int*)  d_in[4];
    const int*   receivers    = (const int*)  d_in[5];
    const int*   species      = (const int*)  d_in[6];
    const float* W_in_s       = (const float*)d_in[7];
    const float* W_in_v       = (const float*)d_in[8];
    const float* mlp_w1       = (const float*)d_in[9];
    const float* mlp_b1       = (const float*)d_in[10];
    const float* mlp_w2       = (const float*)d_in[11];
    const float* W_out_s      = (const float*)d_in[12];
    const float* W_out_v      = (const float*)d_in[13];
    const float* sc_s         = (const float*)d_in[14];
    const float* sc_v         = (const float*)d_in[15];
    float* out = (float*)d_out;

    zero_kernel<<<(NN * 36 + 255) / 256, 256>>>();
    pre_kernel<<<(2 * NN + 255) / 256, 256>>>(node_scalars, node_vectors, W_in_s, W_in_v);
    edge_kernel<<<(2 * NE + 255) / 256, 256>>>(edge_sh, radial_emb, senders, receivers,
                                               mlp_w1, mlp_b1, mlp_w2);
    post_kernel<<<(2 * NN + 255) / 256, 256>>>(node_scalars, node_vectors, species,
                                               W_out_s, W_out_v, sc_s, sc_v, out);
}